// round 1
// baseline (speedup 1.0000x reference)
#include <cuda_runtime.h>
#include <cuda_bf16.h>

#define NN 100000
#define NE 3200000
#define DD 64
#define NG 125
#define SCAN_BLK 512
#define SCAN_NBLK 196   // ceil(100000/512)

// ---------------- scratch (static device globals; no allocs) ----------------
__device__ float g_hA[NN * DD];     // GEMM output / agg input
__device__ float g_hB[NN * DD];     // agg output / next GEMM input
__device__ int   g_cnt[NN];         // in-degree counts
__device__ float g_dinv[NN];        // 1/sqrt(deg+1)
__device__ int   g_excl[NN];        // per-block exclusive scan
__device__ int   g_bsum[SCAN_NBLK]; // block sums
__device__ int   g_rowptr[NN + 1];  // CSR row pointers (by dst)
__device__ int   g_cursor[NN];      // bucket cursors
__device__ int   g_esrc[NE];        // CSR: source node per edge
__device__ float g_ew[NE];          // CSR: norm weight per edge
__device__ float g_pool[NG * DD];   // pooled means

// ---------------- build CSR ----------------
__global__ void k_zero_cnt() {
    int i = blockIdx.x * blockDim.x + threadIdx.x;
    if (i < NN) g_cnt[i] = 0;
}

__global__ void k_hist(const int* __restrict__ dst) {
    int i = blockIdx.x * blockDim.x + threadIdx.x;
    if (i < NE) atomicAdd(&g_cnt[dst[i]], 1);
}

__global__ void k_dinv() {
    int i = blockIdx.x * blockDim.x + threadIdx.x;
    if (i < NN) g_dinv[i] = rsqrtf((float)g_cnt[i] + 1.0f);
}

__global__ void k_scan1() {
    __shared__ int sh[SCAN_BLK];
    int t = threadIdx.x;
    int i = blockIdx.x * SCAN_BLK + t;
    int v = (i < NN) ? g_cnt[i] : 0;
    sh[t] = v;
    __syncthreads();
    #pragma unroll
    for (int off = 1; off < SCAN_BLK; off <<= 1) {
        int a = (t >= off) ? sh[t - off] : 0;
        __syncthreads();
        sh[t] += a;
        __syncthreads();
    }
    if (i < NN) g_excl[i] = sh[t] - v;       // exclusive within block
    if (t == SCAN_BLK - 1) g_bsum[blockIdx.x] = sh[t];
}

__global__ void k_scan2() {
    if (threadIdx.x == 0) {
        int acc = 0;
        for (int b = 0; b < SCAN_NBLK; b++) {
            int tmp = g_bsum[b];
            g_bsum[b] = acc;
            acc += tmp;
        }
    }
}

__global__ void k_scan3() {
    int i = blockIdx.x * blockDim.x + threadIdx.x;
    if (i < NN) {
        int r = g_excl[i] + g_bsum[i / SCAN_BLK];
        g_rowptr[i] = r;
        g_cursor[i] = r;
    }
    if (i == 0) g_rowptr[NN] = NE;
}

__global__ void k_bucket(const int* __restrict__ src, const int* __restrict__ dst) {
    int e = blockIdx.x * blockDim.x + threadIdx.x;
    if (e < NE) {
        int s = src[e];
        int d = dst[e];
        int pos = atomicAdd(&g_cursor[d], 1);
        g_esrc[pos] = s;
        g_ew[pos] = g_dinv[s] * g_dinv[d];
    }
}

// ---------------- dense GEMM: [rows,64] @ [64,64] -> g_hA ----------------
// block = 256 threads, 32 rows per block. W fully in SMEM.
__device__ __forceinline__ void gemm_body(const float* __restrict__ X,
                                          const float* __restrict__ W,
                                          float* __restrict__ H) {
    __shared__ float Ws[DD * DD];
    __shared__ float Xs[32 * DD];
    int t = threadIdx.x;
    const float4* W4 = (const float4*)W;
    float4* Ws4 = (float4*)Ws;
    #pragma unroll
    for (int j = t; j < DD * DD / 4; j += 256) Ws4[j] = W4[j];
    int row0 = blockIdx.x * 32;
    const float4* X4 = (const float4*)(X + (size_t)row0 * DD);
    float4* Xs4 = (float4*)Xs;
    #pragma unroll
    for (int j = t; j < 32 * DD / 4; j += 256) Xs4[j] = X4[j];
    __syncthreads();

    int r  = t >> 3;          // 0..31 row within tile
    int cg = (t & 7) * 8;     // 8 columns per thread
    float acc[8] = {0.f, 0.f, 0.f, 0.f, 0.f, 0.f, 0.f, 0.f};
    const float* xrow = Xs + r * DD;
    #pragma unroll
    for (int k = 0; k < DD; k++) {
        float xv = xrow[k];
        float4 w0 = *(const float4*)&Ws[k * DD + cg];
        float4 w1 = *(const float4*)&Ws[k * DD + cg + 4];
        acc[0] += xv * w0.x; acc[1] += xv * w0.y;
        acc[2] += xv * w0.z; acc[3] += xv * w0.w;
        acc[4] += xv * w1.x; acc[5] += xv * w1.y;
        acc[6] += xv * w1.z; acc[7] += xv * w1.w;
    }
    float* out = H + (size_t)(row0 + r) * DD + cg;
    *(float4*)out       = make_float4(acc[0], acc[1], acc[2], acc[3]);
    *(float4*)(out + 4) = make_float4(acc[4], acc[5], acc[6], acc[7]);
}

__global__ void k_gemm_x(const float* __restrict__ X, const float* __restrict__ W) {
    gemm_body(X, W, g_hA);      // x @ W1 -> hA
}
__global__ void k_gemm_h(const float* __restrict__ W) {
    gemm_body(g_hB, W, g_hA);   // hB @ W2 -> hA
}

// ---------------- aggregation: warp per node, CSR gather, no float atomics --
// reads g_hA, writes g_hB = relu( sum_e w_e * hA[src_e] + dinv^2 * hA[i] + b )
__global__ void k_agg(const float* __restrict__ bias) {
    int gtid = blockIdx.x * blockDim.x + threadIdx.x;
    int node = gtid >> 5;                  // exactly NN warps launched
    int lane = threadIdx.x & 31;
    int start = g_rowptr[node];
    int end   = g_rowptr[node + 1];

    float2 acc = make_float2(0.f, 0.f);
    for (int e0 = start; e0 < end; e0 += 32) {
        int n = end - e0;
        if (n > 32) n = 32;
        int s = 0; float w = 0.f;
        if (lane < n) {
            s = g_esrc[e0 + lane];
            w = g_ew[e0 + lane];
        }
        for (int j = 0; j < n; j++) {
            int   sj = __shfl_sync(0xffffffffu, s, j);
            float wj = __shfl_sync(0xffffffffu, w, j);
            float2 hv = *(const float2*)&g_hA[(size_t)sj * DD + lane * 2];
            acc.x += wj * hv.x;
            acc.y += wj * hv.y;
        }
    }
    float di = g_dinv[node];
    float sl = di * di;
    float2 hs = *(const float2*)&g_hA[(size_t)node * DD + lane * 2];
    acc.x += sl * hs.x + bias[lane * 2];
    acc.y += sl * hs.y + bias[lane * 2 + 1];
    acc.x = fmaxf(acc.x, 0.f);
    acc.y = fmaxf(acc.y, 0.f);
    *(float2*)&g_hB[(size_t)node * DD + lane * 2] = acc;
}

// ---------------- per-graph mean pool of g_hB ----------------
__global__ void k_pool(const int* __restrict__ ptr) {
    int g = blockIdx.x;
    int t = threadIdx.x;              // 256 threads
    int c = t & 63;
    int rg = t >> 6;                  // 4 row groups
    int start = ptr[g];
    int end   = ptr[g + 1];
    float acc = 0.f;
    for (int r = start + rg; r < end; r += 4)
        acc += g_hB[(size_t)r * DD + c];
    __shared__ float sh[256];
    sh[t] = acc;
    __syncthreads();
    if (t < 64) {
        float s = sh[t] + sh[t + 64] + sh[t + 128] + sh[t + 192];
        g_pool[g * DD + t] = s / (float)(end - start);
    }
}

// ---------------- final tiny GEMM: pool @ Wf + bf -> out ----------------
__global__ void k_final(const float* __restrict__ Wf, const float* __restrict__ bf,
                        float* __restrict__ out) {
    __shared__ float p[DD];
    int g = blockIdx.x;
    int c = threadIdx.x;
    p[c] = g_pool[g * DD + c];
    __syncthreads();
    float acc = bf[c];
    #pragma unroll
    for (int k = 0; k < DD; k++)
        acc += p[k] * Wf[k * DD + c];
    out[g * DD + c] = acc;
}

// ---------------- launch ----------------
extern "C" void kernel_launch(void* const* d_in, const int* in_sizes, int n_in,
                              void* d_out, int out_size) {
    const float* x   = (const float*)d_in[0];
    const int*   ei  = (const int*)d_in[1];
    const int*   src = ei;
    const int*   dst = ei + NE;
    const int*   ptr = (const int*)d_in[2];
    const float* W1  = (const float*)d_in[3];
    const float* b1  = (const float*)d_in[4];
    const float* W2  = (const float*)d_in[5];
    const float* b2  = (const float*)d_in[6];
    const float* Wf  = (const float*)d_in[7];
    const float* bf  = (const float*)d_in[8];
    float* out = (float*)d_out;

    // CSR build (reused by both layers)
    k_zero_cnt<<<(NN + 255) / 256, 256>>>();
    k_hist<<<(NE + 511) / 512, 512>>>(dst);
    k_dinv<<<(NN + 255) / 256, 256>>>();
    k_scan1<<<SCAN_NBLK, SCAN_BLK>>>();
    k_scan2<<<1, 32>>>();
    k_scan3<<<(NN + 255) / 256, 256>>>();
    k_bucket<<<(NE + 255) / 256, 256>>>(src, dst);

    // layer 1
    k_gemm_x<<<NN / 32, 256>>>(x, W1);
    k_agg<<<NN * 32 / 256, 256>>>(b1);
    // layer 2
    k_gemm_h<<<NN / 32, 256>>>(W2);
    k_agg<<<NN * 32 / 256, 256>>>(b2);
    // pool then project (mean commutes with the linear head)
    k_pool<<<NG, 256>>>(ptr);
    k_final<<<NG, DD>>>(Wf, bf, out);
}

// round 2
// speedup vs baseline: 1.7713x; 1.7713x over previous
#include <cuda_runtime.h>
#include <cuda_bf16.h>

#define NN 100000
#define NE 3200000
#define DD 64
#define NG 125
#define SCAN_BLK 512
#define SCAN_NBLK 196   // ceil(100000/512)

typedef unsigned long long ull;

// ---------------- scratch (static device globals; no allocs) ----------------
__device__ __align__(256) float g_hA[NN * DD];   // GEMM output (pre-scaled by dinv)
__device__ __align__(256) float g_hB[NN * DD];   // agg output / next GEMM input
__device__ int   g_cnt[NN];
__device__ float g_dinv[NN];
__device__ int   g_excl[NN];
__device__ int   g_bsum[SCAN_NBLK];
__device__ int   g_rowptr[NN + 1];
__device__ int   g_cursor[NN];
__device__ __align__(16) int g_esrc[NE];         // CSR by dst: source node per edge
__device__ __align__(16) float g_pool[NG * DD];

// ---------------- f32x2 packed math helpers ----------------
__device__ __forceinline__ ull f32x2_fma(ull a, ull b, ull c) {
    ull d;
    asm("fma.rn.f32x2 %0, %1, %2, %3;" : "=l"(d) : "l"(a), "l"(b), "l"(c));
    return d;
}
__device__ __forceinline__ ull f32_dup(float x) {
    ull d;
    unsigned u = __float_as_uint(x);
    asm("mov.b64 %0, {%1, %1};" : "=l"(d) : "r"(u));
    return d;
}
__device__ __forceinline__ void f32x2_unpack(ull v, float& lo, float& hi) {
    unsigned a, b;
    asm("mov.b64 {%0, %1}, %2;" : "=r"(a), "=r"(b) : "l"(v));
    lo = __uint_as_float(a);
    hi = __uint_as_float(b);
}

// ---------------- build CSR ----------------
__global__ void k_zero_cnt() {
    int i = blockIdx.x * blockDim.x + threadIdx.x;
    if (i < NN) g_cnt[i] = 0;
}

__global__ void k_hist(const int* __restrict__ dst) {
    int i = blockIdx.x * blockDim.x + threadIdx.x;
    if (i < NE) atomicAdd(&g_cnt[dst[i]], 1);
}

__global__ void k_dinv() {
    int i = blockIdx.x * blockDim.x + threadIdx.x;
    if (i < NN) g_dinv[i] = rsqrtf((float)g_cnt[i] + 1.0f);
}

__global__ void k_scan1() {
    __shared__ int sh[SCAN_BLK];
    int t = threadIdx.x;
    int i = blockIdx.x * SCAN_BLK + t;
    int v = (i < NN) ? g_cnt[i] : 0;
    sh[t] = v;
    __syncthreads();
    #pragma unroll
    for (int off = 1; off < SCAN_BLK; off <<= 1) {
        int a = (t >= off) ? sh[t - off] : 0;
        __syncthreads();
        sh[t] += a;
        __syncthreads();
    }
    if (i < NN) g_excl[i] = sh[t] - v;
    if (t == SCAN_BLK - 1) g_bsum[blockIdx.x] = sh[t];
}

__global__ void k_scan2() {
    if (threadIdx.x == 0) {
        int acc = 0;
        #pragma unroll 4
        for (int b = 0; b < SCAN_NBLK; b++) {
            int tmp = g_bsum[b];
            g_bsum[b] = acc;
            acc += tmp;
        }
    }
}

__global__ void k_scan3() {
    int i = blockIdx.x * blockDim.x + threadIdx.x;
    if (i < NN) {
        int r = g_excl[i] + g_bsum[i / SCAN_BLK];
        g_rowptr[i] = r;
        g_cursor[i] = r;
    }
    if (i == 0) g_rowptr[NN] = NE;
}

__global__ void k_bucket(const int* __restrict__ src, const int* __restrict__ dst) {
    int e = blockIdx.x * blockDim.x + threadIdx.x;
    if (e < NE) {
        int d = dst[e];
        int pos = atomicAdd(&g_cursor[d], 1);
        g_esrc[pos] = src[e];
    }
}

// ---------------- GEMM: H[r,:] = (X[r,:] @ W) * dinv[r] ----------------
// block = 128 threads, tile = 64 rows x 64 cols; thread computes 4 rows x 8 cols
// using packed f32x2 FMA.
__global__ void __launch_bounds__(128) k_gemm(const float* __restrict__ X,
                                              const float* __restrict__ W,
                                              float* __restrict__ H) {
    __shared__ float Xs[64][68];   // padded: x column reads hit distinct banks
    __shared__ float Ws[64][64];
    int t = threadIdx.x;
    int row0 = blockIdx.x * 64;

    #pragma unroll
    for (int j = t; j < 64 * 16; j += 128)
        ((float4*)Ws)[j] = ((const float4*)W)[j];
    #pragma unroll
    for (int j = t; j < 64 * 16; j += 128) {
        int r = j >> 4, c = j & 15;
        float4 v = make_float4(0.f, 0.f, 0.f, 0.f);
        if (row0 + r < NN) v = *(const float4*)&X[(size_t)(row0 + r) * DD + c * 4];
        *(float4*)&Xs[r][c * 4] = v;
    }
    __syncthreads();

    int tc = t & 7;          // 8 col groups of 8
    int tr = t >> 3;         // 16 row groups of 4
    ull acc[4][4];
    #pragma unroll
    for (int i = 0; i < 4; i++)
        #pragma unroll
        for (int j = 0; j < 4; j++) acc[i][j] = 0ull;

    #pragma unroll 16
    for (int k = 0; k < 64; k++) {
        ulonglong2 wa = *(const ulonglong2*)&Ws[k][tc * 8];       // cols 0..3
        ulonglong2 wb = *(const ulonglong2*)&Ws[k][tc * 8 + 4];   // cols 4..7
        #pragma unroll
        for (int i = 0; i < 4; i++) {
            ull xd = f32_dup(Xs[tr * 4 + i][k]);
            acc[i][0] = f32x2_fma(xd, wa.x, acc[i][0]);
            acc[i][1] = f32x2_fma(xd, wa.y, acc[i][1]);
            acc[i][2] = f32x2_fma(xd, wb.x, acc[i][2]);
            acc[i][3] = f32x2_fma(xd, wb.y, acc[i][3]);
        }
    }

    #pragma unroll
    for (int i = 0; i < 4; i++) {
        int r = row0 + tr * 4 + i;
        if (r < NN) {
            float di = g_dinv[r];
            float o[8];
            #pragma unroll
            for (int j = 0; j < 4; j++) {
                f32x2_unpack(acc[i][j], o[j * 2], o[j * 2 + 1]);
                o[j * 2]     *= di;
                o[j * 2 + 1] *= di;
            }
            float* out = H + (size_t)r * DD + tc * 8;
            *(float4*)out       = make_float4(o[0], o[1], o[2], o[3]);
            *(float4*)(out + 4) = make_float4(o[4], o[5], o[6], o[7]);
        }
    }
}

// ---------------- aggregation: warp per node, 2 edges/iter x 4-deep unroll --
// hB[d] = relu( (Sum_e hA[src_e] + hA[d]) * dinv[d] + b )
__global__ void __launch_bounds__(256) k_agg(const float* __restrict__ bias) {
    int gtid = blockIdx.x * blockDim.x + threadIdx.x;
    int node = gtid >> 5;
    int lane = threadIdx.x & 31;
    int half = lane >> 4;      // 0: even edges, 1: odd edges
    int c4   = lane & 15;      // float4 column group
    int e   = g_rowptr[node];
    int end = g_rowptr[node + 1];

    float4 acc = make_float4(0.f, 0.f, 0.f, 0.f);

    for (; e + 8 <= end; e += 8) {
        int s0 = g_esrc[e + 0], s1 = g_esrc[e + 1];
        int s2 = g_esrc[e + 2], s3 = g_esrc[e + 3];
        int s4 = g_esrc[e + 4], s5 = g_esrc[e + 5];
        int s6 = g_esrc[e + 6], s7 = g_esrc[e + 7];
        int a0 = half ? s1 : s0;
        int a1 = half ? s3 : s2;
        int a2 = half ? s5 : s4;
        int a3 = half ? s7 : s6;
        float4 v0 = *(const float4*)&g_hA[(size_t)a0 * DD + c4 * 4];
        float4 v1 = *(const float4*)&g_hA[(size_t)a1 * DD + c4 * 4];
        float4 v2 = *(const float4*)&g_hA[(size_t)a2 * DD + c4 * 4];
        float4 v3 = *(const float4*)&g_hA[(size_t)a3 * DD + c4 * 4];
        acc.x += (v0.x + v1.x) + (v2.x + v3.x);
        acc.y += (v0.y + v1.y) + (v2.y + v3.y);
        acc.z += (v0.z + v1.z) + (v2.z + v3.z);
        acc.w += (v0.w + v1.w) + (v2.w + v3.w);
    }
    for (; e < end; e += 2) {
        int idx = e + half;
        if (idx < end) {
            int s = g_esrc[idx];
            float4 v = *(const float4*)&g_hA[(size_t)s * DD + c4 * 4];
            acc.x += v.x; acc.y += v.y; acc.z += v.z; acc.w += v.w;
        }
    }

    acc.x += __shfl_xor_sync(0xffffffffu, acc.x, 16);
    acc.y += __shfl_xor_sync(0xffffffffu, acc.y, 16);
    acc.z += __shfl_xor_sync(0xffffffffu, acc.z, 16);
    acc.w += __shfl_xor_sync(0xffffffffu, acc.w, 16);

    if (half == 0) {
        float4 hs = *(const float4*)&g_hA[(size_t)node * DD + c4 * 4];
        float di = g_dinv[node];
        float4 b = *(const float4*)&bias[c4 * 4];
        float4 o;
        o.x = fmaxf((acc.x + hs.x) * di + b.x, 0.f);
        o.y = fmaxf((acc.y + hs.y) * di + b.y, 0.f);
        o.z = fmaxf((acc.z + hs.z) * di + b.z, 0.f);
        o.w = fmaxf((acc.w + hs.w) * di + b.w, 0.f);
        *(float4*)&g_hB[(size_t)node * DD + c4 * 4] = o;
    }
}

// ---------------- per-graph mean pool of g_hB ----------------
__global__ void k_pool(const int* __restrict__ ptr) {
    int g = blockIdx.x;
    int t = threadIdx.x;              // 512 threads
    int c = t & 63;
    int rg = t >> 6;                  // 8 row groups
    int start = ptr[g];
    int end   = ptr[g + 1];
    float acc = 0.f;
    for (int r = start + rg; r < end; r += 8)
        acc += g_hB[(size_t)r * DD + c];
    __shared__ float sh[512];
    sh[t] = acc;
    __syncthreads();
    if (t < 64) {
        float s = 0.f;
        #pragma unroll
        for (int j = 0; j < 8; j++) s += sh[t + j * 64];
        g_pool[g * DD + t] = s / (float)(end - start);
    }
}

// ---------------- final tiny GEMM: pool @ Wf + bf -> out ----------------
__global__ void k_final(const float* __restrict__ Wf, const float* __restrict__ bf,
                        float* __restrict__ out) {
    __shared__ float p[DD];
    int g = blockIdx.x;
    int c = threadIdx.x;
    p[c] = g_pool[g * DD + c];
    __syncthreads();
    float acc = bf[c];
    #pragma unroll
    for (int k = 0; k < DD; k++)
        acc += p[k] * Wf[k * DD + c];
    out[g * DD + c] = acc;
}

// ---------------- launch ----------------
extern "C" void kernel_launch(void* const* d_in, const int* in_sizes, int n_in,
                              void* d_out, int out_size) {
    const float* x   = (const float*)d_in[0];
    const int*   ei  = (const int*)d_in[1];
    const int*   src = ei;
    const int*   dst = ei + NE;
    const int*   ptr = (const int*)d_in[2];
    const float* W1  = (const float*)d_in[3];
    const float* b1  = (const float*)d_in[4];
    const float* W2  = (const float*)d_in[5];
    const float* b2  = (const float*)d_in[6];
    const float* Wf  = (const float*)d_in[7];
    const float* bf  = (const float*)d_in[8];
    float* out = (float*)d_out;

    float* hA;  cudaGetSymbolAddress((void**)&hA, g_hA);
    float* hB;  cudaGetSymbolAddress((void**)&hB, g_hB);

    // CSR build (shared by both layers)
    k_zero_cnt<<<(NN + 255) / 256, 256>>>();
    k_hist<<<(NE + 511) / 512, 512>>>(dst);
    k_dinv<<<(NN + 255) / 256, 256>>>();
    k_scan1<<<SCAN_NBLK, SCAN_BLK>>>();
    k_scan2<<<1, 32>>>();
    k_scan3<<<(NN + 255) / 256, 256>>>();
    k_bucket<<<(NE + 255) / 256, 256>>>(src, dst);

    // layer 1
    k_gemm<<<(NN + 63) / 64, 128>>>(x, W1, hA);
    k_agg<<<NN * 32 / 256, 256>>>(b1);
    // layer 2
    k_gemm<<<(NN + 63) / 64, 128>>>(hB, W2, hA);
    k_agg<<<NN * 32 / 256, 256>>>(b2);
    // pool then project (mean commutes with the linear head)
    k_pool<<<NG, 512>>>(ptr);
    k_final<<<NG, DD>>>(Wf, bf, out);
}

// round 3
// speedup vs baseline: 1.7805x; 1.0052x over previous
#include <cuda_runtime.h>
#include <cuda_fp16.h>
#include <cuda_bf16.h>

#define NN 100000
#define NE 3200000
#define DD 64
#define NG 125
#define SCAN_BLK 512
#define SCAN_NBLK 196   // ceil(100000/512)

typedef unsigned long long ull;

// ---------------- scratch (static device globals; no allocs) ----------------
__device__ __align__(256) __half g_hAh[NN * DD]; // GEMM output (pre-scaled by dinv), fp16
__device__ __align__(256) float  g_hB[NN * DD];  // agg output / next GEMM input, fp32
__device__ int   g_cnt[NN];
__device__ float g_dinv[NN];
__device__ int   g_excl[NN];
__device__ int   g_bsum[SCAN_NBLK];
__device__ int   g_rowptr[NN + 1];
__device__ int   g_cursor[NN];
__device__ __align__(16) int g_esrc[NE];         // CSR by dst: source node per edge
__device__ __align__(16) float g_pool[NG * DD];

// ---------------- f32x2 packed math helpers ----------------
__device__ __forceinline__ ull f32x2_fma(ull a, ull b, ull c) {
    ull d;
    asm("fma.rn.f32x2 %0, %1, %2, %3;" : "=l"(d) : "l"(a), "l"(b), "l"(c));
    return d;
}
__device__ __forceinline__ ull f32_dup(float x) {
    ull d;
    unsigned u = __float_as_uint(x);
    asm("mov.b64 %0, {%1, %1};" : "=l"(d) : "r"(u));
    return d;
}
__device__ __forceinline__ void f32x2_unpack(ull v, float& lo, float& hi) {
    unsigned a, b;
    asm("mov.b64 {%0, %1}, %2;" : "=r"(a), "=r"(b) : "l"(v));
    lo = __uint_as_float(a);
    hi = __uint_as_float(b);
}

// ---------------- build CSR ----------------
__global__ void k_hist(const int* __restrict__ dst) {
    int i = blockIdx.x * blockDim.x + threadIdx.x;   // NE/4 threads
    const int4* d4 = (const int4*)dst;
    int4 v = d4[i];
    atomicAdd(&g_cnt[v.x], 1);
    atomicAdd(&g_cnt[v.y], 1);
    atomicAdd(&g_cnt[v.z], 1);
    atomicAdd(&g_cnt[v.w], 1);
}

__global__ void k_dinv() {
    int i = blockIdx.x * blockDim.x + threadIdx.x;
    if (i < NN) g_dinv[i] = rsqrtf((float)g_cnt[i] + 1.0f);
}

__global__ void k_scan1() {
    __shared__ int sh[SCAN_BLK];
    int t = threadIdx.x;
    int i = blockIdx.x * SCAN_BLK + t;
    int v = (i < NN) ? g_cnt[i] : 0;
    sh[t] = v;
    __syncthreads();
    #pragma unroll
    for (int off = 1; off < SCAN_BLK; off <<= 1) {
        int a = (t >= off) ? sh[t - off] : 0;
        __syncthreads();
        sh[t] += a;
        __syncthreads();
    }
    if (i < NN) g_excl[i] = sh[t] - v;
    if (t == SCAN_BLK - 1) g_bsum[blockIdx.x] = sh[t];
}

__global__ void k_scan2() {
    if (threadIdx.x == 0) {
        int acc = 0;
        #pragma unroll 4
        for (int b = 0; b < SCAN_NBLK; b++) {
            int tmp = g_bsum[b];
            g_bsum[b] = acc;
            acc += tmp;
        }
    }
}

__global__ void k_scan3() {
    int i = blockIdx.x * blockDim.x + threadIdx.x;
    if (i < NN) {
        int r = g_excl[i] + g_bsum[i / SCAN_BLK];
        g_rowptr[i] = r;
        g_cursor[i] = r;
    }
    if (i == 0) g_rowptr[NN] = NE;
}

__global__ void k_bucket(const int* __restrict__ src, const int* __restrict__ dst) {
    int i = blockIdx.x * blockDim.x + threadIdx.x;   // NE/4 threads
    const int4* s4 = (const int4*)src;
    const int4* d4 = (const int4*)dst;
    int4 s = s4[i];
    int4 d = d4[i];
    g_esrc[atomicAdd(&g_cursor[d.x], 1)] = s.x;
    g_esrc[atomicAdd(&g_cursor[d.y], 1)] = s.y;
    g_esrc[atomicAdd(&g_cursor[d.z], 1)] = s.z;
    g_esrc[atomicAdd(&g_cursor[d.w], 1)] = s.w;
}

// ---------------- GEMM: H[r,:] = half( (X[r,:] @ W) * dinv[r] ) --------------
// block = 128 threads, tile = 64 rows x 64 cols; thread computes 4 rows x 8 cols
__global__ void __launch_bounds__(128) k_gemm(const float* __restrict__ X,
                                              const float* __restrict__ W,
                                              __half* __restrict__ H) {
    __shared__ float Xs[64][68];
    __shared__ float Ws[64][64];
    int t = threadIdx.x;
    int row0 = blockIdx.x * 64;

    #pragma unroll
    for (int j = t; j < 64 * 16; j += 128)
        ((float4*)Ws)[j] = ((const float4*)W)[j];
    #pragma unroll
    for (int j = t; j < 64 * 16; j += 128) {
        int r = j >> 4, c = j & 15;
        float4 v = make_float4(0.f, 0.f, 0.f, 0.f);
        if (row0 + r < NN) v = *(const float4*)&X[(size_t)(row0 + r) * DD + c * 4];
        *(float4*)&Xs[r][c * 4] = v;
    }
    __syncthreads();

    int tc = t & 7;          // 8 col groups of 8
    int tr = t >> 3;         // 16 row groups of 4
    ull acc[4][4];
    #pragma unroll
    for (int i = 0; i < 4; i++)
        #pragma unroll
        for (int j = 0; j < 4; j++) acc[i][j] = 0ull;

    #pragma unroll 16
    for (int k = 0; k < 64; k++) {
        ulonglong2 wa = *(const ulonglong2*)&Ws[k][tc * 8];
        ulonglong2 wb = *(const ulonglong2*)&Ws[k][tc * 8 + 4];
        #pragma unroll
        for (int i = 0; i < 4; i++) {
            ull xd = f32_dup(Xs[tr * 4 + i][k]);
            acc[i][0] = f32x2_fma(xd, wa.x, acc[i][0]);
            acc[i][1] = f32x2_fma(xd, wa.y, acc[i][1]);
            acc[i][2] = f32x2_fma(xd, wb.x, acc[i][2]);
            acc[i][3] = f32x2_fma(xd, wb.y, acc[i][3]);
        }
    }

    #pragma unroll
    for (int i = 0; i < 4; i++) {
        int r = row0 + tr * 4 + i;
        if (r < NN) {
            float di = g_dinv[r];
            __half2 o2[4];
            #pragma unroll
            for (int j = 0; j < 4; j++) {
                float lo, hi;
                f32x2_unpack(acc[i][j], lo, hi);
                o2[j] = __floats2half2_rn(lo * di, hi * di);
            }
            *(uint4*)&H[(size_t)r * DD + tc * 8] =
                *(uint4*)o2;   // 8 halves = 16B
        }
    }
}

// ---------------- aggregation: warp per node, fp16 gather -------------------
// hB[d] = relu( (Sum_e hA[src_e] + hA[d]) * dinv[d] + b ), hA in half
__global__ void __launch_bounds__(256) k_agg(const float* __restrict__ bias) {
    int gtid = blockIdx.x * blockDim.x + threadIdx.x;
    int node = gtid >> 5;
    int lane = threadIdx.x & 31;
    int q  = lane >> 3;       // edge slot 0..3
    int c8 = lane & 7;        // 16B chunk (8 halves) within 128B row
    int e   = g_rowptr[node];
    int end = g_rowptr[node + 1];

    float acc[8] = {0.f, 0.f, 0.f, 0.f, 0.f, 0.f, 0.f, 0.f};

    // 8 edges per iteration (2 x 4 edge slots) -> 8 independent 128B gathers/warp
    for (; e + 8 <= end; e += 8) {
        int s0 = g_esrc[e + q];
        int s1 = g_esrc[e + 4 + q];
        uint4 a = *(const uint4*)&g_hAh[(size_t)s0 * DD + c8 * 8];
        uint4 b = *(const uint4*)&g_hAh[(size_t)s1 * DD + c8 * 8];
        const __half2* ha = (const __half2*)&a;
        const __half2* hb = (const __half2*)&b;
        #pragma unroll
        for (int j = 0; j < 4; j++) {
            float2 fa = __half22float2(ha[j]);
            float2 fb = __half22float2(hb[j]);
            acc[j * 2]     += fa.x + fb.x;
            acc[j * 2 + 1] += fa.y + fb.y;
        }
    }
    for (; e + 4 <= end; e += 4) {
        int s = g_esrc[e + q];
        uint4 a = *(const uint4*)&g_hAh[(size_t)s * DD + c8 * 8];
        const __half2* ha = (const __half2*)&a;
        #pragma unroll
        for (int j = 0; j < 4; j++) {
            float2 fa = __half22float2(ha[j]);
            acc[j * 2]     += fa.x;
            acc[j * 2 + 1] += fa.y;
        }
    }
    {
        int rem = end - e;
        if (q < rem) {
            int s = g_esrc[e + q];
            uint4 a = *(const uint4*)&g_hAh[(size_t)s * DD + c8 * 8];
            const __half2* ha = (const __half2*)&a;
            #pragma unroll
            for (int j = 0; j < 4; j++) {
                float2 fa = __half22float2(ha[j]);
                acc[j * 2]     += fa.x;
                acc[j * 2 + 1] += fa.y;
            }
        }
    }

    // reduce across the 4 edge slots (lanes with equal c8)
    #pragma unroll
    for (int j = 0; j < 8; j++) {
        acc[j] += __shfl_xor_sync(0xffffffffu, acc[j], 8);
        acc[j] += __shfl_xor_sync(0xffffffffu, acc[j], 16);
    }

    if (q == 0) {
        uint4 hs4 = *(const uint4*)&g_hAh[(size_t)node * DD + c8 * 8];
        const __half2* hs = (const __half2*)&hs4;
        float di = g_dinv[node];
        float4 b0 = *(const float4*)&bias[c8 * 8];
        float4 b1 = *(const float4*)&bias[c8 * 8 + 4];
        float o[8];
        #pragma unroll
        for (int j = 0; j < 4; j++) {
            float2 fs = __half22float2(hs[j]);
            o[j * 2]     = acc[j * 2]     + fs.x;
            o[j * 2 + 1] = acc[j * 2 + 1] + fs.y;
        }
        o[0] = fmaxf(o[0] * di + b0.x, 0.f);
        o[1] = fmaxf(o[1] * di + b0.y, 0.f);
        o[2] = fmaxf(o[2] * di + b0.z, 0.f);
        o[3] = fmaxf(o[3] * di + b0.w, 0.f);
        o[4] = fmaxf(o[4] * di + b1.x, 0.f);
        o[5] = fmaxf(o[5] * di + b1.y, 0.f);
        o[6] = fmaxf(o[6] * di + b1.z, 0.f);
        o[7] = fmaxf(o[7] * di + b1.w, 0.f);
        float* out = &g_hB[(size_t)node * DD + c8 * 8];
        *(float4*)out       = make_float4(o[0], o[1], o[2], o[3]);
        *(float4*)(out + 4) = make_float4(o[4], o[5], o[6], o[7]);
    }
}

// ---------------- per-graph mean pool of g_hB ----------------
__global__ void k_pool(const int* __restrict__ ptr) {
    int g = blockIdx.x;
    int t = threadIdx.x;              // 512 threads
    int c = t & 63;
    int rg = t >> 6;                  // 8 row groups
    int start = ptr[g];
    int end   = ptr[g + 1];
    float acc = 0.f;
    for (int r = start + rg; r < end; r += 8)
        acc += g_hB[(size_t)r * DD + c];
    __shared__ float sh[512];
    sh[t] = acc;
    __syncthreads();
    if (t < 64) {
        float s = 0.f;
        #pragma unroll
        for (int j = 0; j < 8; j++) s += sh[t + j * 64];
        g_pool[g * DD + t] = s / (float)(end - start);
    }
}

// ---------------- final tiny GEMM: pool @ Wf + bf -> out ----------------
__global__ void k_final(const float* __restrict__ Wf, const float* __restrict__ bf,
                        float* __restrict__ out) {
    __shared__ float p[DD];
    int g = blockIdx.x;
    int c = threadIdx.x;
    p[c] = g_pool[g * DD + c];
    __syncthreads();
    float acc = bf[c];
    #pragma unroll
    for (int k = 0; k < DD; k++)
        acc += p[k] * Wf[k * DD + c];
    out[g * DD + c] = acc;
}

// ---------------- launch ----------------
extern "C" void kernel_launch(void* const* d_in, const int* in_sizes, int n_in,
                              void* d_out, int out_size) {
    const float* x   = (const float*)d_in[0];
    const int*   ei  = (const int*)d_in[1];
    const int*   src = ei;
    const int*   dst = ei + NE;
    const int*   ptr = (const int*)d_in[2];
    const float* W1  = (const float*)d_in[3];
    const float* b1  = (const float*)d_in[4];
    const float* W2  = (const float*)d_in[5];
    const float* b2  = (const float*)d_in[6];
    const float* Wf  = (const float*)d_in[7];
    const float* bf  = (const float*)d_in[8];
    float* out = (float*)d_out;

    __half* hA; cudaGetSymbolAddress((void**)&hA, g_hAh);
    float*  hB; cudaGetSymbolAddress((void**)&hB, g_hB);
    int*    cnt; cudaGetSymbolAddress((void**)&cnt, g_cnt);

    // CSR build (shared by both layers)
    cudaMemsetAsync(cnt, 0, NN * sizeof(int));
    k_hist<<<NE / 4 / 256, 256>>>(dst);
    k_dinv<<<(NN + 255) / 256, 256>>>();
    k_scan1<<<SCAN_NBLK, SCAN_BLK>>>();
    k_scan2<<<1, 32>>>();
    k_scan3<<<(NN + 255) / 256, 256>>>();
    k_bucket<<<NE / 4 / 256, 256>>>(src, dst);

    // layer 1
    k_gemm<<<(NN + 63) / 64, 128>>>(x, W1, hA);
    k_agg<<<NN * 32 / 256, 256>>>(b1);
    // layer 2
    k_gemm<<<(NN + 63) / 64, 128>>>(hB, W2, hA);
    k_agg<<<NN * 32 / 256, 256>>>(b2);
    // pool then project (mean commutes with the linear head)
    k_pool<<<NG, 512>>>(ptr);
    k_final<<<NG, DD>>>(Wf, bf, out);
}